// round 12
// baseline (speedup 1.0000x reference)
#include <cuda_runtime.h>

#define NPTS 120000
#define INC  256
#define MIDC 64
#define OUTC 256
#define KNB  27
#define EPSV 1e-5f

typedef unsigned long long u64;
typedef unsigned int u32;

// ---- f32x2 packed helpers ----
__device__ __forceinline__ u64 pk2(float a) {
    u64 r; asm("mov.b64 %0,{%1,%1};" : "=l"(r) : "f"(a)); return r;
}
__device__ __forceinline__ void fma2(u64& d, u64 a, u64 b) {
    asm("fma.rn.f32x2 %0,%1,%2,%0;" : "+l"(d) : "l"(a), "l"(b));
}
__device__ __forceinline__ float2 up2(u64 v) {
    float2 r; asm("mov.b64 {%0,%1},%2;" : "=f"(r.x), "=f"(r.y) : "l"(v)); return r;
}

// ---- cp.async (used only in k_gemm1, which has passed repeatedly) ----
__device__ __forceinline__ u32 sptr(const void* p) { return (u32)__cvta_generic_to_shared(p); }
__device__ __forceinline__ void cpa16(u32 d, const void* s) {
    asm volatile("cp.async.ca.shared.global [%0],[%1],16;" :: "r"(d), "l"(s));
}
__device__ __forceinline__ void cpa_commit() { asm volatile("cp.async.commit_group;"); }
template<int N> __device__ __forceinline__ void cpa_wait() {
    asm volatile("cp.async.wait_group %0;" :: "n"(N));
}

// ---------------- scratch ----------------
__device__ float g_h1[(size_t)NPTS * MIDC];
__device__ float g_r1[(size_t)NPTS * MIDC];
__device__ float g_h2[(size_t)NPTS * MIDC];
__device__ float g_h3[(size_t)NPTS * OUTC];
__device__ float g_sum1[MIDC], g_ssq1[MIDC];
__device__ float g_sum2[MIDC], g_ssq2[MIDC], g_a2[MIDC], g_c2[MIDC];
__device__ float g_sum3[OUTC], g_ssq3[OUTC], g_a3[OUTC], g_c3[OUTC];

__global__ void k_zero() {
    int t = threadIdx.x;
    if (t < MIDC) { g_sum1[t] = 0.f; g_ssq1[t] = 0.f; g_sum2[t] = 0.f; g_ssq2[t] = 0.f; }
    g_sum3[t] = 0.f; g_ssq3[t] = 0.f;
}

// stats over a 128x64 block tile (outf zeros for invalid rows)
__device__ __forceinline__ void block_stats8(float outf[8][4], float* s0, float* s1,
                                             int tid, int col0,
                                             float* gsum, float* gssq, int colbase) {
    float s[4] = {}, q[4] = {};
#pragma unroll
    for (int i = 0; i < 8; i++)
#pragma unroll
        for (int j = 0; j < 4; j++) { float v = outf[i][j]; s[j] += v; q[j] += v * v; }
    __syncthreads();
    int rg = tid >> 4;
#pragma unroll
    for (int j = 0; j < 4; j++) {
        s0[rg * 64 + col0 + j] = s[j];
        s1[rg * 64 + col0 + j] = q[j];
    }
    __syncthreads();
    if (tid < 64) {
        float S = 0.f, Q = 0.f;
#pragma unroll
        for (int g = 0; g < 16; g++) { S += s0[g * 64 + tid]; Q += s1[g * 64 + tid]; }
        atomicAdd(&gsum[colbase + tid], S);
        atomicAdd(&gssq[colbase + tid], Q);
    }
}

// 128x64 += 128x64 @ 64x64, stride-64 smem tiles (f32x2 SIMT)
__device__ __forceinline__ void mm_tile64(const float* As, const float* Bs,
                                          int row0, int col0, u64 acc[8][2]) {
#pragma unroll 8
    for (int kk = 0; kk < 64; kk += 2) {
        ulonglong2 bv0 = *(const ulonglong2*)&Bs[kk * 64 + col0];
        ulonglong2 bv1 = *(const ulonglong2*)&Bs[(kk + 1) * 64 + col0];
#pragma unroll
        for (int i = 0; i < 8; i++) {
            float2 a = *(const float2*)&As[(row0 + i) * 64 + kk];
            u64 a0 = pk2(a.x), a1 = pk2(a.y);
            fma2(acc[i][0], a0, bv0.x);
            fma2(acc[i][1], a0, bv0.y);
            fma2(acc[i][0], a1, bv1.x);
            fma2(acc[i][1], a1, bv1.y);
        }
    }
}

// ---------------- GEMM1: g_h1 = x @ W1; cp.async pipelined; fused stats ----------------
__global__ __launch_bounds__(256) void k_gemm1(const float* __restrict__ x,
                                               const float* __restrict__ W1) {
    extern __shared__ float smem[];
    float* As = smem;
    float* Bs = smem + 2 * 128 * 64;
    const int tid  = threadIdx.x;
    const int p0   = blockIdx.x * 128;
    const int nval = (NPTS - p0 < 128) ? (NPTS - p0) : 128;
    const int row0 = (tid >> 4) << 3;
    const int col0 = (tid & 15) << 2;
    u64 acc[8][2] = {};

    auto issue = [&](int kc, int buf) {
        float* Ad = As + buf * 8192;
        float* Bd = Bs + buf * 4096;
#pragma unroll
        for (int i = 0; i < 8; i++) {
            int j4 = tid + i * 256;
            int r = j4 >> 4, c = (j4 & 15) << 2;
            int re = (r < nval) ? r : 0;
            cpa16(sptr(&Ad[r * 64 + c]), x + (size_t)(p0 + re) * INC + kc * 64 + c);
        }
#pragma unroll
        for (int i = 0; i < 4; i++) {
            int j4 = tid + i * 256;
            int r = j4 >> 4, c = (j4 & 15) << 2;
            cpa16(sptr(&Bd[r * 64 + c]), W1 + (size_t)(kc * 64 + r) * MIDC + c);
        }
        cpa_commit();
    };

    issue(0, 0);
    for (int kc = 0; kc < 4; kc++) {
        int cur = kc & 1;
        if (kc + 1 < 4) { issue(kc + 1, cur ^ 1); cpa_wait<1>(); }
        else cpa_wait<0>();
        __syncthreads();
        mm_tile64(As + cur * 8192, Bs + cur * 4096, row0, col0, acc);
        __syncthreads();
    }

    float outf[8][4];
#pragma unroll
    for (int i = 0; i < 8; i++) {
        float2 p = up2(acc[i][0]), q = up2(acc[i][1]);
        bool v = (row0 + i) < nval;
        outf[i][0] = v ? p.x : 0.f; outf[i][1] = v ? p.y : 0.f;
        outf[i][2] = v ? q.x : 0.f; outf[i][3] = v ? q.y : 0.f;
        if (v)
            *(float4*)&g_h1[(size_t)(p0 + row0 + i) * MIDC + col0] =
                make_float4(p.x, p.y, q.x, q.y);
    }
    block_stats8(outf, As, Bs, tid, col0, g_sum1, g_ssq1, 0);
}

// ---------------- norm1 (finalize1 inlined): g_r1 = relu(bn1(g_h1)) ----------------
__global__ __launch_bounds__(256) void k_norm1(const float* __restrict__ g1,
                                               const float* __restrict__ b1) {
    const size_t tid0 = (size_t)blockIdx.x * blockDim.x + threadIdx.x;
    const int c = (int)((tid0 * 4) & (MIDC - 1));
    float a[4], cc[4];
#pragma unroll
    for (int j = 0; j < 4; j++) {
        float m = g_sum1[c + j] * (1.f / NPTS);
        float v = g_ssq1[c + j] * (1.f / NPTS) - m * m;
        float ai = g1[c + j] * rsqrtf(v + EPSV);
        a[j] = ai; cc[j] = b1[c + j] - m * ai;
    }
    const size_t total4 = (size_t)NPTS * MIDC / 4;
    for (size_t i4 = tid0; i4 < total4; i4 += (size_t)gridDim.x * blockDim.x) {
        float4 v = *(const float4*)&g_h1[i4 * 4];
        v.x = fmaxf(fmaf(v.x, a[0], cc[0]), 0.f);
        v.y = fmaxf(fmaf(v.y, a[1], cc[1]), 0.f);
        v.z = fmaxf(fmaf(v.z, a[2], cc[2]), 0.f);
        v.w = fmaxf(fmaf(v.w, a[3], cc[3]), 0.f);
        *(float4*)&g_r1[i4 * 4] = v;
    }
}

// ---------------- gather GEMM: 64x64 tiles, dup-A f32x2 SIMT, fully register-staged ----------------
// NO async primitives: only LDG -> registers -> STS, double-buffered, uniform __syncthreads.
// smem floats: A0[64*132], A1[64*132] (u64 dup pairs, row stride 66 u64),
//              B0[64*64], B1[64*64], sidx[64*27]
#define AFL (64 * 132)
#define GSM_FLOATS (2 * AFL + 2 * 64 * 64 + (64 * KNB))
#define GSM_BYTES  (GSM_FLOATS * 4)

__global__ __launch_bounds__(256) void k_gather(const int* __restrict__ nbr,
                                                const float* __restrict__ W3) {
    extern __shared__ float smem[];
    float* A0 = smem;
    float* A1 = smem + AFL;
    float* B0 = smem + 2 * AFL;
    float* B1 = B0 + 64 * 64;
    int*   sidx = (int*)(B1 + 64 * 64);
    const int tid = threadIdx.x;
    const int p0  = blockIdx.x * 64;   // NPTS = 64*1875 exactly -> no guards

    for (int i = tid; i < 64 * KNB; i += 256) sidx[i] = nbr[(size_t)p0 * KNB + i];
    __syncthreads();

    const int cfill = tid & 63;   // channel this thread fills
    const int rf0   = tid >> 6;   // row lane 0..3
    float v[16];
    float4 b4[4];

    auto load_regs = [&](int k) {
#pragma unroll
        for (int i = 0; i < 16; i++) {
            int ridx = sidx[(rf0 + 4 * i) * KNB + k];
            v[i] = __ldg(&g_r1[(size_t)ridx * MIDC + cfill]);
        }
        const float4* wb = (const float4*)(W3 + (size_t)k * MIDC * MIDC);
#pragma unroll
        for (int i = 0; i < 4; i++) b4[i] = __ldg(wb + tid + i * 256);
    };
    auto sts_regs = [&](int buf) {
        u64* Ad = (u64*)(buf ? A1 : A0);
#pragma unroll
        for (int i = 0; i < 16; i++) Ad[(rf0 + 4 * i) * 66 + cfill] = pk2(v[i]);
        float4* Bd = (float4*)(buf ? B1 : B0);
#pragma unroll
        for (int i = 0; i < 4; i++) Bd[tid + i * 256] = b4[i];
    };

    const int row0 = (tid >> 3) << 1;   // 0..62 step 2
    const int col0 = (tid & 7) << 3;    // 0..56 step 8
    u64 acc[2][4] = {};

    load_regs(0);
    for (int k = 0; k < KNB; k++) {
        const int cur = k & 1;
        sts_regs(cur);                      // consume v/b4 for tile k
        if (k + 1 < KNB) load_regs(k + 1);  // LDGs overlap compute(k) below
        __syncthreads();

        const u64* Ad = (const u64*)(cur ? A1 : A0) + row0 * 66;
        const float* Bp = (cur ? B1 : B0) + col0;
#pragma unroll 16
        for (int kk = 0; kk < 64; kk++) {
            ulonglong2 b01 = *(const ulonglong2*)(Bp + kk * 64);
            ulonglong2 b23 = *(const ulonglong2*)(Bp + kk * 64 + 4);
            u64 a0 = Ad[kk];
            u64 a1 = Ad[66 + kk];
            fma2(acc[0][0], a0, b01.x); fma2(acc[0][1], a0, b01.y);
            fma2(acc[0][2], a0, b23.x); fma2(acc[0][3], a0, b23.y);
            fma2(acc[1][0], a1, b01.x); fma2(acc[1][1], a1, b01.y);
            fma2(acc[1][2], a1, b23.x); fma2(acc[1][3], a1, b23.y);
        }
        __syncthreads();
    }

#pragma unroll
    for (int rr = 0; rr < 2; rr++) {
        float2 q0 = up2(acc[rr][0]), q1 = up2(acc[rr][1]);
        float2 q2 = up2(acc[rr][2]), q3 = up2(acc[rr][3]);
        float* d = &g_h2[(size_t)(p0 + row0 + rr) * MIDC + col0];
        *(float4*)d       = make_float4(q0.x, q0.y, q1.x, q1.y);
        *(float4*)(d + 4) = make_float4(q2.x, q2.y, q3.x, q3.y);
    }
}

// ---------------- column stats for g_h2 [N,64] ----------------
__global__ __launch_bounds__(256) void k_stats2() {
    int tid = threadIdx.x;
    int c = tid & 63, sub = tid >> 6;
    float s = 0.f, q = 0.f;
    for (int r = blockIdx.x * 4 + sub; r < NPTS; r += gridDim.x * 4) {
        float v = g_h2[(size_t)r * MIDC + c];
        s += v; q += v * v;
    }
    __shared__ float ss[256], qq[256];
    ss[tid] = s; qq[tid] = q;
    __syncthreads();
    if (tid < 64) {
        s = ss[tid] + ss[tid + 64] + ss[tid + 128] + ss[tid + 192];
        q = qq[tid] + qq[tid + 64] + qq[tid + 128] + qq[tid + 192];
        atomicAdd(&g_sum2[tid], s);
        atomicAdd(&g_ssq2[tid], q);
    }
}

// ---------------- BN finalize (which: 1 -> mid2, 2 -> out) ----------------
__global__ void k_finalize(const float* __restrict__ g, const float* __restrict__ b, int which) {
    int i = threadIdx.x;
    int C = (which == 2) ? OUTC : MIDC;
    if (i >= C) return;
    const float* sum = (which == 1) ? g_sum2 : g_sum3;
    const float* ssq = (which == 1) ? g_ssq2 : g_ssq3;
    float* a = (which == 1) ? g_a2 : g_a3;
    float* c = (which == 1) ? g_c2 : g_c3;
    float m = sum[i] * (1.f / NPTS);
    float v = ssq[i] * (1.f / NPTS) - m * m;
    float ai = g[i] * rsqrtf(v + EPSV);
    a[i] = ai;
    c[i] = b[i] - m * ai;
}

// ---------------- GEMM2: g_h3 = relu(bn2(g_h2)) @ W2; fused stats ----------------
__global__ __launch_bounds__(256) void k_gemm2(const float* __restrict__ W2) {
    extern __shared__ float smem[];
    float* As = smem;
    float* Bs = smem + 128 * 64;
    float* sa = smem + 192 * 64;
    float* sc = sa + MIDC;
    const int tid = threadIdx.x;
    const int p0  = blockIdx.x * 128;
    const int cb  = blockIdx.y * 64;
    const int nval = (NPTS - p0 < 128) ? (NPTS - p0) : 128;
    if (tid < MIDC) { sa[tid] = g_a2[tid]; sc[tid] = g_c2[tid]; }
    __syncthreads();
#pragma unroll
    for (int i = 0; i < 8; i++) {
        int j4 = tid + i * 256;
        int r = j4 >> 4, c = (j4 & 15) << 2;
        int re = (r < nval) ? r : 0;
        float4 v = *(const float4*)&g_h2[(size_t)(p0 + re) * MIDC + c];
        v.x = fmaxf(fmaf(v.x, sa[c + 0], sc[c + 0]), 0.f);
        v.y = fmaxf(fmaf(v.y, sa[c + 1], sc[c + 1]), 0.f);
        v.z = fmaxf(fmaf(v.z, sa[c + 2], sc[c + 2]), 0.f);
        v.w = fmaxf(fmaf(v.w, sa[c + 3], sc[c + 3]), 0.f);
        *(float4*)&As[r * 64 + c] = v;
    }
#pragma unroll
    for (int i = 0; i < 4; i++) {
        int j4 = tid + i * 256;
        int r = j4 >> 4, c = (j4 & 15) << 2;
        *(float4*)&Bs[r * 64 + c] = *(const float4*)(W2 + (size_t)r * OUTC + cb + c);
    }
    __syncthreads();
    const int row0 = (tid >> 4) << 3;
    const int col0 = (tid & 15) << 2;
    u64 acc[8][2] = {};
    mm_tile64(As, Bs, row0, col0, acc);

    float outf[8][4];
#pragma unroll
    for (int i = 0; i < 8; i++) {
        float2 p = up2(acc[i][0]), q = up2(acc[i][1]);
        bool v = (row0 + i) < nval;
        outf[i][0] = v ? p.x : 0.f; outf[i][1] = v ? p.y : 0.f;
        outf[i][2] = v ? q.x : 0.f; outf[i][3] = v ? q.y : 0.f;
        if (v)
            *(float4*)&g_h3[(size_t)(p0 + row0 + i) * OUTC + cb + col0] =
                make_float4(p.x, p.y, q.x, q.y);
    }
    block_stats8(outf, As, Bs, tid, col0, g_sum3, g_ssq3, cb);
}

// ---------------- epilogue: out = relu(bn3(h3) + x) ----------------
__global__ __launch_bounds__(256) void k_out(const float* __restrict__ x,
                                             float* __restrict__ out) {
    const size_t total4 = (size_t)NPTS * OUTC / 4;
    for (size_t i4 = (size_t)blockIdx.x * blockDim.x + threadIdx.x; i4 < total4;
         i4 += (size_t)gridDim.x * blockDim.x) {
        int c = (int)((i4 * 4) & (OUTC - 1));
        float4 h  = *(const float4*)&g_h3[i4 * 4];
        float4 xv = ((const float4*)x)[i4];
        float4 o;
        o.x = fmaxf(fmaf(h.x, g_a3[c + 0], g_c3[c + 0]) + xv.x, 0.f);
        o.y = fmaxf(fmaf(h.y, g_a3[c + 1], g_c3[c + 1]) + xv.y, 0.f);
        o.z = fmaxf(fmaf(h.z, g_a3[c + 2], g_c3[c + 2]) + xv.z, 0.f);
        o.w = fmaxf(fmaf(h.w, g_a3[c + 3], g_c3[c + 3]) + xv.w, 0.f);
        ((float4*)out)[i4] = o;
    }
}

// ---------------- launch ----------------
extern "C" void kernel_launch(void* const* d_in, const int* in_sizes, int n_in,
                              void* d_out, int out_size) {
    const float* x   = (const float*)d_in[0];
    const int*   nbr = (const int*)d_in[1];
    const float* W1  = (const float*)d_in[2];
    const float* W3  = (const float*)d_in[3];
    const float* W2  = (const float*)d_in[4];
    const float* g1  = (const float*)d_in[5];
    const float* b1  = (const float*)d_in[6];
    const float* g2  = (const float*)d_in[7];
    const float* b2  = (const float*)d_in[8];
    const float* g3  = (const float*)d_in[9];
    const float* b3  = (const float*)d_in[10];
    float* out = (float*)d_out;

    const int SM_G1 = (2 * 128 * 64 + 2 * 64 * 64) * 4;           // 96 KB
    const int SM_G2 = (128 * 64 + 64 * 64) * 4 + 2 * MIDC * 4;    // ~48.5 KB
    static bool attr_done = false;
    if (!attr_done) {
        cudaFuncSetAttribute(k_gemm1, cudaFuncAttributeMaxDynamicSharedMemorySize, SM_G1);
        cudaFuncSetAttribute(k_gather, cudaFuncAttributeMaxDynamicSharedMemorySize, GSM_BYTES);
        cudaFuncSetAttribute(k_gemm2, cudaFuncAttributeMaxDynamicSharedMemorySize, SM_G2);
        attr_done = true;
    }

    const int GB128 = (NPTS + 127) / 128;  // 938
    const int GB64  = NPTS / 64;           // 1875, exact
    k_zero<<<1, 256>>>();                                   // 0
    k_gemm1<<<GB128, 256, SM_G1>>>(x, W1);                  // 1
    k_norm1<<<2048, 256>>>(g1, b1);                         // 2
    k_gather<<<GB64, 256, GSM_BYTES>>>(nbr, W3);            // 3  <- ncu capture slot
    k_stats2<<<512, 256>>>();                               // 4
    k_finalize<<<1, 256>>>(g2, b2, 1);                      // 5
    dim3 grid2(GB128, 4);
    k_gemm2<<<grid2, 256, SM_G2>>>(W2);                     // 6
    k_finalize<<<1, 256>>>(g3, b3, 2);                      // 7
    k_out<<<2048, 256>>>(x, out);                           // 8
}

// round 14
// speedup vs baseline: 2.2882x; 2.2882x over previous
#include <cuda_runtime.h>

#define NPTS 120000
#define INC  256
#define MIDC 64
#define OUTC 256
#define KNB  27
#define EPSV 1e-5f

typedef unsigned long long u64;
typedef unsigned int u32;

// ---- f32x2 packed helpers ----
__device__ __forceinline__ u64 pk2(float a) {
    u64 r; asm("mov.b64 %0,{%1,%1};" : "=l"(r) : "f"(a)); return r;
}
__device__ __forceinline__ void fma2(u64& d, u64 a, u64 b) {
    asm("fma.rn.f32x2 %0,%1,%2,%0;" : "+l"(d) : "l"(a), "l"(b));
}
__device__ __forceinline__ float2 up2(u64 v) {
    float2 r; asm("mov.b64 {%0,%1},%2;" : "=f"(r.x), "=f"(r.y) : "l"(v)); return r;
}

// ---- cp.async ----
__device__ __forceinline__ u32 sptr(const void* p) { return (u32)__cvta_generic_to_shared(p); }
__device__ __forceinline__ void cpa16(u32 d, const void* s) {
    asm volatile("cp.async.ca.shared.global [%0],[%1],16;" :: "r"(d), "l"(s));
}
__device__ __forceinline__ void cpa_commit() { asm volatile("cp.async.commit_group;"); }
template<int N> __device__ __forceinline__ void cpa_wait() {
    asm volatile("cp.async.wait_group %0;" :: "n"(N));
}

// ---------------- scratch ----------------
__device__ float g_h1[(size_t)NPTS * MIDC];
__device__ float g_r1[(size_t)NPTS * MIDC];
__device__ float g_h2[(size_t)NPTS * MIDC];
__device__ float g_h3[(size_t)NPTS * OUTC];
__device__ float g_sum1[MIDC], g_ssq1[MIDC], g_a1[MIDC], g_c1[MIDC];
__device__ float g_sum2[MIDC], g_ssq2[MIDC], g_a2[MIDC], g_c2[MIDC];
__device__ float g_sum3[OUTC], g_ssq3[OUTC], g_a3[OUTC], g_c3[OUTC];

__global__ void k_zero() {
    int t = threadIdx.x;
    if (t < MIDC) { g_sum1[t] = 0.f; g_ssq1[t] = 0.f; g_sum2[t] = 0.f; g_ssq2[t] = 0.f; }
    g_sum3[t] = 0.f; g_ssq3[t] = 0.f;
}

// stats over a 128x64 block tile (outf zeros for invalid rows)
__device__ __forceinline__ void block_stats8(float outf[8][4], float* s0, float* s1,
                                             int tid, int col0,
                                             float* gsum, float* gssq, int colbase) {
    float s[4] = {}, q[4] = {};
#pragma unroll
    for (int i = 0; i < 8; i++)
#pragma unroll
        for (int j = 0; j < 4; j++) { float v = outf[i][j]; s[j] += v; q[j] += v * v; }
    __syncthreads();
    int rg = tid >> 4;
#pragma unroll
    for (int j = 0; j < 4; j++) {
        s0[rg * 64 + col0 + j] = s[j];
        s1[rg * 64 + col0 + j] = q[j];
    }
    __syncthreads();
    if (tid < 64) {
        float S = 0.f, Q = 0.f;
#pragma unroll
        for (int g = 0; g < 16; g++) { S += s0[g * 64 + tid]; Q += s1[g * 64 + tid]; }
        atomicAdd(&gsum[colbase + tid], S);
        atomicAdd(&gssq[colbase + tid], Q);
    }
}

// 128x64 += 128x64 @ 64x64, stride-64 smem tiles.
// A loaded as float4 per 4 kk (halves LDS count, kills in-loop splat pressure vs round-4 form).
__device__ __forceinline__ void mm_tile64(const float* As, const float* Bs,
                                          int row0, int col0, u64 acc[8][2]) {
#pragma unroll
    for (int k4 = 0; k4 < 64; k4 += 4) {
        float4 a4[8];
#pragma unroll
        for (int i = 0; i < 8; i++)
            a4[i] = *(const float4*)&As[(row0 + i) * 64 + k4];
#pragma unroll
        for (int j = 0; j < 4; j++) {
            ulonglong2 bv = *(const ulonglong2*)&Bs[(k4 + j) * 64 + col0];
#pragma unroll
            for (int i = 0; i < 8; i++) {
                float a = (j == 0) ? a4[i].x : (j == 1) ? a4[i].y
                        : (j == 2) ? a4[i].z : a4[i].w;
                u64 av = pk2(a);
                fma2(acc[i][0], av, bv.x);
                fma2(acc[i][1], av, bv.y);
            }
        }
    }
}

// ---------------- GEMM1: g_h1 = x @ W1; cp.async pipelined; fused stats ----------------
__global__ __launch_bounds__(256) void k_gemm1(const float* __restrict__ x,
                                               const float* __restrict__ W1) {
    extern __shared__ float smem[];
    float* As = smem;
    float* Bs = smem + 2 * 128 * 64;
    const int tid  = threadIdx.x;
    const int p0   = blockIdx.x * 128;
    const int nval = (NPTS - p0 < 128) ? (NPTS - p0) : 128;
    const int row0 = (tid >> 4) << 3;
    const int col0 = (tid & 15) << 2;
    u64 acc[8][2] = {};

    auto issue = [&](int kc, int buf) {
        float* Ad = As + buf * 8192;
        float* Bd = Bs + buf * 4096;
#pragma unroll
        for (int i = 0; i < 8; i++) {
            int j4 = tid + i * 256;
            int r = j4 >> 4, c = (j4 & 15) << 2;
            int re = (r < nval) ? r : 0;
            cpa16(sptr(&Ad[r * 64 + c]), x + (size_t)(p0 + re) * INC + kc * 64 + c);
        }
#pragma unroll
        for (int i = 0; i < 4; i++) {
            int j4 = tid + i * 256;
            int r = j4 >> 4, c = (j4 & 15) << 2;
            cpa16(sptr(&Bd[r * 64 + c]), W1 + (size_t)(kc * 64 + r) * MIDC + c);
        }
        cpa_commit();
    };

    issue(0, 0);
    for (int kc = 0; kc < 4; kc++) {
        int cur = kc & 1;
        if (kc + 1 < 4) { issue(kc + 1, cur ^ 1); cpa_wait<1>(); }
        else cpa_wait<0>();
        __syncthreads();
        mm_tile64(As + cur * 8192, Bs + cur * 4096, row0, col0, acc);
        __syncthreads();
    }

    float outf[8][4];
#pragma unroll
    for (int i = 0; i < 8; i++) {
        float2 p = up2(acc[i][0]), q = up2(acc[i][1]);
        bool v = (row0 + i) < nval;
        outf[i][0] = v ? p.x : 0.f; outf[i][1] = v ? p.y : 0.f;
        outf[i][2] = v ? q.x : 0.f; outf[i][3] = v ? q.y : 0.f;
        if (v)
            *(float4*)&g_h1[(size_t)(p0 + row0 + i) * MIDC + col0] =
                make_float4(p.x, p.y, q.x, q.y);
    }
    block_stats8(outf, As, Bs, tid, col0, g_sum1, g_ssq1, 0);
}

// ---------------- BN finalize ----------------
__global__ void k_finalize(const float* __restrict__ g, const float* __restrict__ b, int which) {
    int i = threadIdx.x;
    int C = (which == 2) ? OUTC : MIDC;
    if (i >= C) return;
    const float* sum = (which == 0) ? g_sum1 : (which == 1) ? g_sum2 : g_sum3;
    const float* ssq = (which == 0) ? g_ssq1 : (which == 1) ? g_ssq2 : g_ssq3;
    float* a = (which == 0) ? g_a1 : (which == 1) ? g_a2 : g_a3;
    float* c = (which == 0) ? g_c1 : (which == 1) ? g_c2 : g_c3;
    float m = sum[i] * (1.f / NPTS);
    float v = ssq[i] * (1.f / NPTS) - m * m;
    float ai = g[i] * rsqrtf(v + EPSV);
    a[i] = ai;
    c[i] = b[i] - m * ai;
}

// ---------------- norm1: g_r1 = relu(bn1(g_h1)) ----------------
__global__ __launch_bounds__(256) void k_norm1() {
    const size_t total4 = (size_t)NPTS * MIDC / 4;
    for (size_t i4 = (size_t)blockIdx.x * blockDim.x + threadIdx.x; i4 < total4;
         i4 += (size_t)gridDim.x * blockDim.x) {
        int c = (int)((i4 * 4) & (MIDC - 1));
        float4 v = *(const float4*)&g_h1[i4 * 4];
        v.x = fmaxf(fmaf(v.x, g_a1[c + 0], g_c1[c + 0]), 0.f);
        v.y = fmaxf(fmaf(v.y, g_a1[c + 1], g_c1[c + 1]), 0.f);
        v.z = fmaxf(fmaf(v.z, g_a1[c + 2], g_c1[c + 2]), 0.f);
        v.w = fmaxf(fmaf(v.w, g_a1[c + 3], g_c1[c + 3]), 0.f);
        *(float4*)&g_r1[i4 * 4] = v;
    }
}

// ---------------- gather GEMM (cp.async pipelined) + fused stats ----------------
__global__ __launch_bounds__(256) void k_gather(const int* __restrict__ nbr,
                                                const float* __restrict__ W3) {
    extern __shared__ float smem[];
    float* As = smem;                      // 2 * 128*64
    float* Bs = smem + 2 * 128 * 64;       // 2 * 64*64
    int*   sidx = (int*)(smem + 2 * 128 * 64 + 2 * 64 * 64); // 128*KNB
    const int tid = threadIdx.x;
    const int p0  = blockIdx.x * 128;
    const int nval = (NPTS - p0 < 128) ? (NPTS - p0) : 128;
    const int row0 = (tid >> 4) << 3;
    const int col0 = (tid & 15) << 2;

    for (int i = tid; i < nval * KNB; i += 256) sidx[i] = nbr[(size_t)p0 * KNB + i];
    __syncthreads();

    auto issue = [&](int k, int buf) {
        float* Bd = Bs + buf * 4096;
        const float* wb = W3 + (size_t)k * MIDC * MIDC;
#pragma unroll
        for (int i = 0; i < 4; i++) {
            int j4 = tid + i * 256;
            int r = j4 >> 4, c = (j4 & 15) << 2;
            cpa16(sptr(&Bd[r * 64 + c]), wb + r * 64 + c);
        }
        float* Ad = As + buf * 8192;
#pragma unroll
        for (int i = 0; i < 8; i++) {
            int j4 = tid + i * 256;
            int r = j4 >> 4, c = (j4 & 15) << 2;
            int ridx = (r < nval) ? sidx[r * KNB + k] : 0;
            cpa16(sptr(&Ad[r * 64 + c]), g_r1 + (size_t)ridx * MIDC + c);
        }
        cpa_commit();
    };

    u64 acc[8][2] = {};
    issue(0, 0);
    for (int k = 0; k < KNB; k++) {
        int cur = k & 1;
        if (k + 1 < KNB) { issue(k + 1, cur ^ 1); cpa_wait<1>(); }
        else cpa_wait<0>();
        __syncthreads();
        mm_tile64(As + cur * 8192, Bs + cur * 4096, row0, col0, acc);
        __syncthreads();
    }

    float outf[8][4];
#pragma unroll
    for (int i = 0; i < 8; i++) {
        float2 p = up2(acc[i][0]), q = up2(acc[i][1]);
        bool v = (row0 + i) < nval;
        outf[i][0] = v ? p.x : 0.f; outf[i][1] = v ? p.y : 0.f;
        outf[i][2] = v ? q.x : 0.f; outf[i][3] = v ? q.y : 0.f;
        if (v)
            *(float4*)&g_h2[(size_t)(p0 + row0 + i) * MIDC + col0] =
                make_float4(p.x, p.y, q.x, q.y);
    }
    block_stats8(outf, As, Bs, tid, col0, g_sum2, g_ssq2, 0);
}

// ---------------- GEMM2: g_h3 = relu(bn2(g_h2)) @ W2; fused stats ----------------
__global__ __launch_bounds__(256) void k_gemm2(const float* __restrict__ W2) {
    extern __shared__ float smem[];
    float* As = smem;             // 128*64
    float* Bs = smem + 128 * 64;  // 64*64
    float* sa = smem + 192 * 64;
    float* sc = sa + MIDC;
    const int tid = threadIdx.x;
    const int p0  = blockIdx.x * 128;
    const int cb  = blockIdx.y * 64;
    const int nval = (NPTS - p0 < 128) ? (NPTS - p0) : 128;
    if (tid < MIDC) { sa[tid] = g_a2[tid]; sc[tid] = g_c2[tid]; }
    __syncthreads();
#pragma unroll
    for (int i = 0; i < 8; i++) {
        int j4 = tid + i * 256;
        int r = j4 >> 4, c = (j4 & 15) << 2;
        int re = (r < nval) ? r : 0;
        float4 v = *(const float4*)&g_h2[(size_t)(p0 + re) * MIDC + c];
        v.x = fmaxf(fmaf(v.x, sa[c + 0], sc[c + 0]), 0.f);
        v.y = fmaxf(fmaf(v.y, sa[c + 1], sc[c + 1]), 0.f);
        v.z = fmaxf(fmaf(v.z, sa[c + 2], sc[c + 2]), 0.f);
        v.w = fmaxf(fmaf(v.w, sa[c + 3], sc[c + 3]), 0.f);
        *(float4*)&As[r * 64 + c] = v;
    }
#pragma unroll
    for (int i = 0; i < 4; i++) {
        int j4 = tid + i * 256;
        int r = j4 >> 4, c = (j4 & 15) << 2;
        *(float4*)&Bs[r * 64 + c] = *(const float4*)(W2 + (size_t)r * OUTC + cb + c);
    }
    __syncthreads();
    const int row0 = (tid >> 4) << 3;
    const int col0 = (tid & 15) << 2;
    u64 acc[8][2] = {};
    mm_tile64(As, Bs, row0, col0, acc);

    float outf[8][4];
#pragma unroll
    for (int i = 0; i < 8; i++) {
        float2 p = up2(acc[i][0]), q = up2(acc[i][1]);
        bool v = (row0 + i) < nval;
        outf[i][0] = v ? p.x : 0.f; outf[i][1] = v ? p.y : 0.f;
        outf[i][2] = v ? q.x : 0.f; outf[i][3] = v ? q.y : 0.f;
        if (v)
            *(float4*)&g_h3[(size_t)(p0 + row0 + i) * OUTC + cb + col0] =
                make_float4(p.x, p.y, q.x, q.y);
    }
    block_stats8(outf, As, Bs, tid, col0, g_sum3, g_ssq3, cb);
}

// ---------------- epilogue: out = relu(bn3(h3) + x) ----------------
__global__ __launch_bounds__(256) void k_out(const float* __restrict__ x,
                                             float* __restrict__ out) {
    const size_t total4 = (size_t)NPTS * OUTC / 4;
    for (size_t i4 = (size_t)blockIdx.x * blockDim.x + threadIdx.x; i4 < total4;
         i4 += (size_t)gridDim.x * blockDim.x) {
        int c = (int)((i4 * 4) & (OUTC - 1));
        float4 h  = *(const float4*)&g_h3[i4 * 4];
        float4 xv = ((const float4*)x)[i4];
        float4 o;
        o.x = fmaxf(fmaf(h.x, g_a3[c + 0], g_c3[c + 0]) + xv.x, 0.f);
        o.y = fmaxf(fmaf(h.y, g_a3[c + 1], g_c3[c + 1]) + xv.y, 0.f);
        o.z = fmaxf(fmaf(h.z, g_a3[c + 2], g_c3[c + 2]) + xv.z, 0.f);
        o.w = fmaxf(fmaf(h.w, g_a3[c + 3], g_c3[c + 3]) + xv.w, 0.f);
        ((float4*)out)[i4] = o;
    }
}

// ---------------- launch ----------------
extern "C" void kernel_launch(void* const* d_in, const int* in_sizes, int n_in,
                              void* d_out, int out_size) {
    const float* x   = (const float*)d_in[0];
    const int*   nbr = (const int*)d_in[1];
    const float* W1  = (const float*)d_in[2];
    const float* W3  = (const float*)d_in[3];
    const float* W2  = (const float*)d_in[4];
    const float* g1  = (const float*)d_in[5];
    const float* b1  = (const float*)d_in[6];
    const float* g2  = (const float*)d_in[7];
    const float* b2  = (const float*)d_in[8];
    const float* g3  = (const float*)d_in[9];
    const float* b3  = (const float*)d_in[10];
    float* out = (float*)d_out;

    const int SM_G1  = (2 * 128 * 64 + 2 * 64 * 64) * 4;                  // 96 KB
    const int SM_GAT = SM_G1 + 128 * KNB * 4;                             // ~109.5 KB
    const int SM_G2  = (128 * 64 + 64 * 64) * 4 + 2 * MIDC * 4;           // ~48.5 KB
    static bool attr_done = false;
    if (!attr_done) {
        cudaFuncSetAttribute(k_gemm1, cudaFuncAttributeMaxDynamicSharedMemorySize, SM_G1);
        cudaFuncSetAttribute(k_gather, cudaFuncAttributeMaxDynamicSharedMemorySize, SM_GAT);
        cudaFuncSetAttribute(k_gemm2, cudaFuncAttributeMaxDynamicSharedMemorySize, SM_G2);
        attr_done = true;
    }

    const int GB = (NPTS + 127) / 128;  // 938
    k_zero<<<1, 256>>>();
    k_gemm1<<<GB, 256, SM_G1>>>(x, W1);
    k_finalize<<<1, 256>>>(g1, b1, 0);
    k_norm1<<<2048, 256>>>();
    k_gather<<<GB, 256, SM_GAT>>>(nbr, W3);
    k_finalize<<<1, 256>>>(g2, b2, 1);
    dim3 grid2(GB, 4);
    k_gemm2<<<grid2, 256, SM_G2>>>(W2);
    k_finalize<<<1, 256>>>(g3, b3, 2);
    k_out<<<2048, 256>>>(x, out);
}